// round 1
// baseline (speedup 1.0000x reference)
#include <cuda_runtime.h>
#include <math.h>

#define NN 100000
#define NE 1600000

#define INV_SQRT_MUL 0.17677669529663687f   /* 1/sqrt(32)  */
#define C_DOT        0.10206207261596575f   /* 1/sqrt(96)  */
#define C_SCL        0.07216878364870323f   /* 1/sqrt(192) */
#define C_CRS        0.05103103630798287f   /* 1/sqrt(384) */
#define SQRT3        1.7320508075688772f

// Scratch (zero-initialized at module load; k_final re-zeros g_acc every launch)
static __device__ __align__(16) float g_acc[(size_t)NN * 256]; // [n][i(32)][dot,sux,suy,suz,cx,cy,cz,one]
static __device__ __align__(16) float g_sc [(size_t)NN * 32];
static __device__ __align__(16) float g_gate[(size_t)NN * 32];
static __device__ __align__(16) float g_hv [(size_t)NN * 96];  // [n][d(3)][i(32)]
static __device__ float g_WA[1024], g_WB[1024], g_WC[1024];

// ---------------------------------------------------------------------------
// K0: fold the two matmul stages + constants into combined 32x32 weights
// WA = W_tp_d @ W_msg_s * C_DOT*INV ; WB = W_tp_s @ W_msg_v * C_SCL*INV ;
// WC = W_tp_c @ W_msg_v * C_CRS*INV
// ---------------------------------------------------------------------------
__global__ void k_combine(const float* __restrict__ Wd, const float* __restrict__ Ws,
                          const float* __restrict__ Wc, const float* __restrict__ Wms,
                          const float* __restrict__ Wmv) {
    int i = threadIdx.x >> 5, j = threadIdx.x & 31;
    float a = 0.f, b = 0.f, c = 0.f;
#pragma unroll
    for (int k = 0; k < 32; k++) {
        float ms = Wms[k * 32 + j], mv = Wmv[k * 32 + j];
        a += Wd[i * 32 + k] * ms;
        b += Ws[i * 32 + k] * mv;
        c += Wc[i * 32 + k] * mv;
    }
    g_WA[i * 32 + j] = a * (C_DOT * INV_SQRT_MUL);
    g_WB[i * 32 + j] = b * (C_SCL * INV_SQRT_MUL);
    g_WC[i * 32 + j] = c * (C_CRS * INV_SQRT_MUL);
}

// ---------------------------------------------------------------------------
// K1a: per-node scalar transform: h_s = s @ W_node_s * INV ; sc = relu(h_s[:32]),
// gate = sigmoid(h_s[32:]).  Thread-per-node, weights broadcast from smem.
// ---------------------------------------------------------------------------
__global__ void k_node_s(const float* __restrict__ x, const float* __restrict__ Wns) {
    __shared__ float w[2048];
    for (int t = threadIdx.x; t < 2048; t += blockDim.x) w[t] = Wns[t] * INV_SQRT_MUL;
    __syncthreads();
    int n = blockIdx.x * blockDim.x + threadIdx.x;
    if (n >= NN) return;
    const float4* xr = reinterpret_cast<const float4*>(x) + (size_t)n * 32;
    float hs[64];
#pragma unroll
    for (int j = 0; j < 64; j++) hs[j] = 0.f;
#pragma unroll 1
    for (int i4 = 0; i4 < 8; i4++) {
        float4 sv = xr[i4];
        const float* wr = &w[i4 * 4 * 64];
#pragma unroll
        for (int j = 0; j < 64; j++) hs[j] += sv.x * wr[j];
#pragma unroll
        for (int j = 0; j < 64; j++) hs[j] += sv.y * wr[64 + j];
#pragma unroll
        for (int j = 0; j < 64; j++) hs[j] += sv.z * wr[128 + j];
#pragma unroll
        for (int j = 0; j < 64; j++) hs[j] += sv.w * wr[192 + j];
    }
    float* scp = g_sc + (size_t)n * 32;
    float* gp  = g_gate + (size_t)n * 32;
#pragma unroll
    for (int j = 0; j < 32; j++) scp[j] = fmaxf(hs[j], 0.f);
#pragma unroll
    for (int j = 0; j < 32; j++) gp[j] = 1.f / (1.f + __expf(-hs[32 + j]));
}

// ---------------------------------------------------------------------------
// K1b: per-node vector transform: h_v[j,d] = sum_i v[i,d] W_node_v[i,j] * INV,
// gated by sigmoid. Stored d-major ([n][d][i]) for coalesced edge gathers.
// ---------------------------------------------------------------------------
__global__ void k_node_v(const float* __restrict__ x, const float* __restrict__ Wnv) {
    __shared__ float w[1024];
    for (int t = threadIdx.x; t < 1024; t += blockDim.x) w[t] = Wnv[t] * INV_SQRT_MUL;
    __syncthreads();
    int n = blockIdx.x * blockDim.x + threadIdx.x;
    if (n >= NN) return;
    const float* vr = x + (size_t)n * 128 + 32;
    float hx[32], hy[32], hz[32];
#pragma unroll
    for (int j = 0; j < 32; j++) { hx[j] = 0.f; hy[j] = 0.f; hz[j] = 0.f; }
#pragma unroll 1
    for (int i = 0; i < 32; i++) {
        float vx = vr[3 * i], vy = vr[3 * i + 1], vz = vr[3 * i + 2];
        const float* wr = &w[i * 32];
#pragma unroll
        for (int j = 0; j < 32; j++) {
            float ww = wr[j];
            hx[j] += vx * ww; hy[j] += vy * ww; hz[j] += vz * ww;
        }
    }
    const float* gp = g_gate + (size_t)n * 32;
    float* o = g_hv + (size_t)n * 96;
#pragma unroll
    for (int j = 0; j < 32; j++) {
        float g = gp[j];
        o[j] = hx[j] * g; o[32 + j] = hy[j] * g; o[64 + j] = hz[j] * g;
    }
}

// ---------------------------------------------------------------------------
// K2: edge kernel. Warp per edge, lane = channel i. Gathers sc/hv of col
// (coalesced 512B), computes dot / cross / scalar*u moments, and reduces into
// the row accumulator with two red.global.add.v4.f32 per lane.
// ---------------------------------------------------------------------------
__device__ __forceinline__ void red4(float* p, float a, float b, float c, float d) {
    asm volatile("red.global.add.v4.f32 [%0], {%1,%2,%3,%4};"
                 :: "l"(p), "f"(a), "f"(b), "f"(c), "f"(d) : "memory");
}

__global__ void k_edge(const int* __restrict__ ei, const float* __restrict__ pos, int E) {
    int e = blockIdx.x * 8 + (threadIdx.x >> 5);
    if (e >= E) return;
    int lane = threadIdx.x & 31;
    int row = __ldg(ei + e);
    int col = __ldg(ei + E + e);
    float rx = __ldg(pos + 3 * col)     - __ldg(pos + 3 * row);
    float ry = __ldg(pos + 3 * col + 1) - __ldg(pos + 3 * row + 1);
    float rz = __ldg(pos + 3 * col + 2) - __ldg(pos + 3 * row + 2);
    float inv = rsqrtf(rx * rx + ry * ry + rz * rz + 1e-12f) * SQRT3;
    // u = sqrt(3) * unit[(1,2,0)]
    float ux = ry * inv, uy = rz * inv, uz = rx * inv;

    const float* hvp = g_hv + (size_t)col * 96;
    float vx = hvp[lane], vy = hvp[32 + lane], vz = hvp[64 + lane];
    float sj = g_sc[(size_t)col * 32 + lane];

    float dot = vx * ux + vy * uy + vz * uz;
    float cx = vy * uz - vz * uy;
    float cy = vz * ux - vx * uz;
    float cz = vx * uy - vy * ux;

    float* base = g_acc + (size_t)row * 256 + lane * 8;
    red4(base,     dot, sj * ux, sj * uy, sj * uz);
    red4(base + 4, cx,  cy,      cz,      1.0f);
}

// ---------------------------------------------------------------------------
// K3: finalize. Thread per node: contract accumulators with combined weights
// (7 FMA per (i,j)), divide by deg, LayerNorm, residual add. Re-zeros g_acc.
// ---------------------------------------------------------------------------
__global__ void __launch_bounds__(128) k_final(const float* __restrict__ x,
                                               const float* __restrict__ gamma,
                                               const float* __restrict__ beta,
                                               float* __restrict__ out) {
    __shared__ float wa[1024], wb[1024], wc[1024], sg[128], sb[128];
    for (int t = threadIdx.x; t < 1024; t += blockDim.x) {
        wa[t] = g_WA[t]; wb[t] = g_WB[t]; wc[t] = g_WC[t];
    }
    for (int t = threadIdx.x; t < 128; t += blockDim.x) { sg[t] = gamma[t]; sb[t] = beta[t]; }
    __syncthreads();
    int n = blockIdx.x * blockDim.x + threadIdx.x;
    if (n >= NN) return;

    float aS[32], aX[32], aY[32], aZ[32];
#pragma unroll
    for (int j = 0; j < 32; j++) { aS[j] = 0.f; aX[j] = 0.f; aY[j] = 0.f; aZ[j] = 0.f; }

    float4* accr = reinterpret_cast<float4*>(g_acc) + (size_t)n * 64;
    float deg = 1.f;
#pragma unroll 1
    for (int i = 0; i < 32; i++) {
        float4 q1 = accr[2 * i];
        float4 q2 = accr[2 * i + 1];
        accr[2 * i]     = make_float4(0.f, 0.f, 0.f, 0.f);
        accr[2 * i + 1] = make_float4(0.f, 0.f, 0.f, 0.f);
        if (i == 0) deg = fmaxf(q2.w, 1.f);
        const float* wA = &wa[i * 32];
        const float* wB = &wb[i * 32];
        const float* wC = &wc[i * 32];
#pragma unroll
        for (int j = 0; j < 32; j++) {
            aS[j] += q1.x * wA[j];
            float b = wB[j], c = wC[j];
            aX[j] += q1.y * b + q2.x * c;
            aY[j] += q1.z * b + q2.y * c;
            aZ[j] += q1.w * b + q2.z * c;
        }
    }

    float invd = 1.f / deg;
    float sum = 0.f, sq = 0.f;
#pragma unroll
    for (int j = 0; j < 32; j++) {
        aS[j] *= invd; aX[j] *= invd; aY[j] *= invd; aZ[j] *= invd;
        sum += aS[j] + aX[j] + aY[j] + aZ[j];
        sq  += aS[j] * aS[j] + aX[j] * aX[j] + aY[j] * aY[j] + aZ[j] * aZ[j];
    }
    float mean = sum * (1.f / 128.f);
    float var  = sq * (1.f / 128.f) - mean * mean;
    float rstd = rsqrtf(fmaxf(var, 0.f) + 1e-5f);

    const float* xr = x + (size_t)n * 128;
    float* op = out + (size_t)n * 128;
#pragma unroll
    for (int j = 0; j < 32; j++)
        op[j] = xr[j] + (aS[j] - mean) * rstd * sg[j] + sb[j];
#pragma unroll
    for (int j = 0; j < 32; j++) {
        int p = 32 + 3 * j;
        op[p]     = xr[p]     + (aX[j] - mean) * rstd * sg[p]     + sb[p];
        op[p + 1] = xr[p + 1] + (aY[j] - mean) * rstd * sg[p + 1] + sb[p + 1];
        op[p + 2] = xr[p + 2] + (aZ[j] - mean) * rstd * sg[p + 2] + sb[p + 2];
    }
}

// ---------------------------------------------------------------------------
extern "C" void kernel_launch(void* const* d_in, const int* in_sizes, int n_in,
                              void* d_out, int out_size) {
    const float* x    = (const float*)d_in[0];
    const float* pos  = (const float*)d_in[1];
    const int*   ei   = (const int*)d_in[2];
    const float* Wns  = (const float*)d_in[3];
    const float* Wnv  = (const float*)d_in[4];
    const float* Wd   = (const float*)d_in[5];
    const float* Ws   = (const float*)d_in[6];
    const float* Wc   = (const float*)d_in[7];
    const float* Wms  = (const float*)d_in[8];
    const float* Wmv  = (const float*)d_in[9];
    const float* gam  = (const float*)d_in[10];
    const float* bet  = (const float*)d_in[11];
    float* out = (float*)d_out;

    int E = in_sizes[2] / 2;
    int nb = (NN + 127) / 128;
    int eb = (E + 7) / 8;            // 8 warps (edges) per 256-thread block

    k_combine<<<1, 1024>>>(Wd, Ws, Wc, Wms, Wmv);
    k_node_s<<<nb, 128>>>(x, Wns);
    k_node_v<<<nb, 128>>>(x, Wnv);
    k_edge<<<eb, 256>>>(ei, pos, E);
    k_final<<<nb, 128>>>(x, gam, bet, out);
}

// round 2
// speedup vs baseline: 5.6943x; 5.6943x over previous
#include <cuda_runtime.h>
#include <math.h>

#define NN 100000
#define NE_MAX 1600000

#define INV_SQRT_MUL 0.17677669529663687f   /* 1/sqrt(32)  */
#define C_DOT        0.10206207261596575f   /* 1/sqrt(96)  */
#define C_SCL        0.07216878364870323f   /* 1/sqrt(192) */
#define C_CRS        0.05103103630798287f   /* 1/sqrt(384) */
#define SQRT3        1.7320508075688772f

#define SCAN_B 1024
#define NB_SCAN ((NN + SCAN_B - 1) / SCAN_B)   /* 98 */

// Scratch (__device__ globals; everything rewritten each launch)
static __device__ __align__(16) float g_feat[(size_t)NN * 128]; // [n][ s(32) | hvx(32) | hvy(32) | hvz(32) ]
static __device__ __align__(16) float4 g_csr[NE_MAX];           // (ux,uy,uz, col-as-int)
static __device__ int g_cnt[NN];
static __device__ int g_rp[NN];
static __device__ int g_cur[NN];
static __device__ int g_bsum[NB_SCAN];
static __device__ float g_WA[1024], g_WB[1024], g_WC[1024];

// ---------------------------------------------------------------------------
// K0: fold both matmul stages + constants: WA = Wtp_d@Wmsg_s, WB = Wtp_s@Wmsg_v,
// WC = Wtp_c@Wmsg_v (with scale constants baked in).
// ---------------------------------------------------------------------------
__global__ void k_combine(const float* __restrict__ Wd, const float* __restrict__ Ws,
                          const float* __restrict__ Wc, const float* __restrict__ Wms,
                          const float* __restrict__ Wmv) {
    int i = threadIdx.x >> 5, j = threadIdx.x & 31;
    float a = 0.f, b = 0.f, c = 0.f;
#pragma unroll
    for (int k = 0; k < 32; k++) {
        float ms = Wms[k * 32 + j], mv = Wmv[k * 32 + j];
        a += Wd[i * 32 + k] * ms;
        b += Ws[i * 32 + k] * mv;
        c += Wc[i * 32 + k] * mv;
    }
    g_WA[i * 32 + j] = a * (C_DOT * INV_SQRT_MUL);
    g_WB[i * 32 + j] = b * (C_SCL * INV_SQRT_MUL);
    g_WC[i * 32 + j] = c * (C_CRS * INV_SQRT_MUL);
}

// ---------------------------------------------------------------------------
// K1: fused node transform, warp per node, fully coalesced.
// g_feat[n] = [ relu(h_s[:32]) | gated h_v (x|y|z, channel-major) ]
// ---------------------------------------------------------------------------
__global__ void __launch_bounds__(256) k_node(const float* __restrict__ x,
                                              const float* __restrict__ Wns,
                                              const float* __restrict__ Wnv) {
    __shared__ float ws_[2048], wv[1024];
    for (int t = threadIdx.x; t < 2048; t += 256) ws_[t] = Wns[t] * INV_SQRT_MUL;
    for (int t = threadIdx.x; t < 1024; t += 256) wv[t] = Wnv[t] * INV_SQRT_MUL;
    __syncthreads();
    int n = blockIdx.x * 8 + (threadIdx.x >> 5);
    if (n >= NN) return;
    int lane = threadIdx.x & 31;
    const float* xr = x + (size_t)n * 128;
    float s0 = xr[lane];
    float v0 = xr[32 + lane], v1 = xr[64 + lane], v2 = xr[96 + lane];

    float h0 = 0.f, h1 = 0.f, hx = 0.f, hy = 0.f, hz = 0.f;
#pragma unroll
    for (int i = 0; i < 32; i++) {
        float si = __shfl_sync(0xffffffffu, s0, i);
        h0 += si * ws_[i * 64 + lane];
        h1 += si * ws_[i * 64 + 32 + lane];
        // v[i][d] lives at flat index 3i+d within (v0,v1,v2); i is compile-time.
        float vxi = ((3 * i) >> 5) == 0 ? v0 : ((3 * i) >> 5) == 1 ? v1 : v2;
        float vyi = ((3 * i + 1) >> 5) == 0 ? v0 : ((3 * i + 1) >> 5) == 1 ? v1 : v2;
        float vzi = ((3 * i + 2) >> 5) == 0 ? v0 : ((3 * i + 2) >> 5) == 1 ? v1 : v2;
        vxi = __shfl_sync(0xffffffffu, vxi, (3 * i) & 31);
        vyi = __shfl_sync(0xffffffffu, vyi, (3 * i + 1) & 31);
        vzi = __shfl_sync(0xffffffffu, vzi, (3 * i + 2) & 31);
        float w = wv[i * 32 + lane];
        hx += vxi * w; hy += vyi * w; hz += vzi * w;
    }
    float sc = fmaxf(h0, 0.f);
    float g = 1.f / (1.f + __expf(-h1));
    float* fp = g_feat + (size_t)n * 128;
    fp[lane] = sc;
    fp[32 + lane] = hx * g;
    fp[64 + lane] = hy * g;
    fp[96 + lane] = hz * g;
}

// ---------------------------------------------------------------------------
// CSR build: zero -> histogram -> scan (3 kernels) -> scatter (+ edge geometry)
// ---------------------------------------------------------------------------
__global__ void k_zero() {
    int i = blockIdx.x * 256 + threadIdx.x;
    if (i < NN) g_cnt[i] = 0;
}

__global__ void k_hist(const int* __restrict__ ei, int E) {
    int e = blockIdx.x * 256 + threadIdx.x;
    if (e < E) atomicAdd(&g_cnt[ei[e]], 1);
}

__global__ void __launch_bounds__(SCAN_B) k_scan1() {
    int i = blockIdx.x * SCAN_B + threadIdx.x;
    int lane = threadIdx.x & 31, wid = threadIdx.x >> 5;
    int v = (i < NN) ? g_cnt[i] : 0;
    int xv = v;
#pragma unroll
    for (int o = 1; o < 32; o <<= 1) {
        int t = __shfl_up_sync(0xffffffffu, xv, o);
        if (lane >= o) xv += t;
    }
    __shared__ int ws[32];
    if (lane == 31) ws[wid] = xv;
    __syncthreads();
    if (threadIdx.x < 32) {
        int y = ws[threadIdx.x];
#pragma unroll
        for (int o = 1; o < 32; o <<= 1) {
            int t = __shfl_up_sync(0xffffffffu, y, o);
            if ((int)threadIdx.x >= o) y += t;
        }
        ws[threadIdx.x] = y;
    }
    __syncthreads();
    int off = wid ? ws[wid - 1] : 0;
    if (i < NN) g_rp[i] = off + xv - v;
    if (threadIdx.x == 0) g_bsum[blockIdx.x] = ws[31];
}

__global__ void k_scan2() {
    int t = threadIdx.x;  // 128 threads, NB_SCAN <= 128
    int v = (t < NB_SCAN) ? g_bsum[t] : 0;
    int xv = v;
#pragma unroll
    for (int o = 1; o < 32; o <<= 1) {
        int u = __shfl_up_sync(0xffffffffu, xv, o);
        if ((t & 31) >= o) xv += u;
    }
    __shared__ int ws[4], wo[4];
    if ((t & 31) == 31) ws[t >> 5] = xv;
    __syncthreads();
    if (t == 0) { int r = 0; for (int k = 0; k < 4; k++) { wo[k] = r; r += ws[k]; } }
    __syncthreads();
    if (t < NB_SCAN) g_bsum[t] = wo[t >> 5] + xv - v;  // exclusive, in place
}

__global__ void __launch_bounds__(SCAN_B) k_scan3() {
    int i = blockIdx.x * SCAN_B + threadIdx.x;
    if (i < NN) {
        int r = g_rp[i] + g_bsum[blockIdx.x];
        g_rp[i] = r;
        g_cur[i] = r;
    }
}

__global__ void k_scatter(const int* __restrict__ ei, const float* __restrict__ pos, int E) {
    int e = blockIdx.x * 256 + threadIdx.x;
    if (e >= E) return;
    int r = __ldg(ei + e);
    int c = __ldg(ei + E + e);
    float rx = __ldg(pos + 3 * c)     - __ldg(pos + 3 * r);
    float ry = __ldg(pos + 3 * c + 1) - __ldg(pos + 3 * r + 1);
    float rz = __ldg(pos + 3 * c + 2) - __ldg(pos + 3 * r + 2);
    float inv = rsqrtf(rx * rx + ry * ry + rz * rz + 1e-12f) * SQRT3;
    // u = sqrt(3) * unit[(1,2,0)]
    float4 rec = make_float4(ry * inv, rz * inv, rx * inv, __int_as_float(c));
    int p = atomicAdd(&g_cur[r], 1);
    g_csr[p] = rec;
}

// ---------------------------------------------------------------------------
// K2: fused aggregate + message transform + LayerNorm + residual.
// Warp per node; 7 moments accumulated in registers (no atomics), then
// shuffle-broadcast contraction with combined weights, warp LN, row write.
// ---------------------------------------------------------------------------
__global__ void __launch_bounds__(256) k_aggregate(const float* __restrict__ x,
                                                   const float* __restrict__ gamma,
                                                   const float* __restrict__ beta,
                                                   float* __restrict__ out) {
    __shared__ float wa[1024], wb[1024], wc[1024], sg[128], sb[128];
    for (int t = threadIdx.x; t < 1024; t += 256) {
        wa[t] = g_WA[t]; wb[t] = g_WB[t]; wc[t] = g_WC[t];
    }
    for (int t = threadIdx.x; t < 128; t += 256) { sg[t] = gamma[t]; sb[t] = beta[t]; }
    __syncthreads();
    int n = blockIdx.x * 8 + (threadIdx.x >> 5);
    if (n >= NN) return;
    int lane = threadIdx.x & 31;

    int start = g_rp[n];
    int count = g_cnt[n];

    float aD = 0.f, aBx = 0.f, aBy = 0.f, aBz = 0.f, aCx = 0.f, aCy = 0.f, aCz = 0.f;
    for (int k = 0; k < count; k++) {
        float4 rec = __ldg(&g_csr[start + k]);       // uniform broadcast load
        int c = __float_as_int(rec.w);
        const float* fp = g_feat + (size_t)c * 128;
        float sj = fp[lane];
        float vx = fp[32 + lane], vy = fp[64 + lane], vz = fp[96 + lane];
        aD  += vx * rec.x + vy * rec.y + vz * rec.z;
        aBx += sj * rec.x; aBy += sj * rec.y; aBz += sj * rec.z;
        aCx += vy * rec.z - vz * rec.y;
        aCy += vz * rec.x - vx * rec.z;
        aCz += vx * rec.y - vy * rec.x;
    }
    float invd = 1.f / fmaxf((float)count, 1.f);
    aD *= invd; aBx *= invd; aBy *= invd; aBz *= invd;
    aCx *= invd; aCy *= invd; aCz *= invd;

    // contraction: out channel j (= lane) accumulates over input channel i
    float aS = 0.f, aX = 0.f, aY = 0.f, aZ = 0.f;
#pragma unroll
    for (int i = 0; i < 32; i++) {
        float d  = __shfl_sync(0xffffffffu, aD, i);
        float bx = __shfl_sync(0xffffffffu, aBx, i);
        float by = __shfl_sync(0xffffffffu, aBy, i);
        float bz = __shfl_sync(0xffffffffu, aBz, i);
        float cx = __shfl_sync(0xffffffffu, aCx, i);
        float cy = __shfl_sync(0xffffffffu, aCy, i);
        float cz = __shfl_sync(0xffffffffu, aCz, i);
        float A = wa[i * 32 + lane], B = wb[i * 32 + lane], C = wc[i * 32 + lane];
        aS += d * A;
        aX += bx * B + cx * C;
        aY += by * B + cy * C;
        aZ += bz * B + cz * C;
    }

    // LayerNorm over the 128 values held across the warp (4 per lane)
    float sum = aS + aX + aY + aZ;
    float sq  = aS * aS + aX * aX + aY * aY + aZ * aZ;
#pragma unroll
    for (int o = 16; o > 0; o >>= 1) {
        sum += __shfl_xor_sync(0xffffffffu, sum, o);
        sq  += __shfl_xor_sync(0xffffffffu, sq, o);
    }
    float mean = sum * (1.f / 128.f);
    float var  = sq * (1.f / 128.f) - mean * mean;
    float rstd = rsqrtf(fmaxf(var, 0.f) + 1e-5f);

    const float* xr = x + (size_t)n * 128;
    float* op = out + (size_t)n * 128;
    op[lane] = xr[lane] + (aS - mean) * rstd * sg[lane] + sb[lane];
    int p = 32 + 3 * lane;
    op[p]     = xr[p]     + (aX - mean) * rstd * sg[p]     + sb[p];
    op[p + 1] = xr[p + 1] + (aY - mean) * rstd * sg[p + 1] + sb[p + 1];
    op[p + 2] = xr[p + 2] + (aZ - mean) * rstd * sg[p + 2] + sb[p + 2];
}

// ---------------------------------------------------------------------------
extern "C" void kernel_launch(void* const* d_in, const int* in_sizes, int n_in,
                              void* d_out, int out_size) {
    const float* x    = (const float*)d_in[0];
    const float* pos  = (const float*)d_in[1];
    const int*   ei   = (const int*)d_in[2];
    const float* Wns  = (const float*)d_in[3];
    const float* Wnv  = (const float*)d_in[4];
    const float* Wd   = (const float*)d_in[5];
    const float* Ws   = (const float*)d_in[6];
    const float* Wc   = (const float*)d_in[7];
    const float* Wms  = (const float*)d_in[8];
    const float* Wmv  = (const float*)d_in[9];
    const float* gam  = (const float*)d_in[10];
    const float* bet  = (const float*)d_in[11];
    float* out = (float*)d_out;

    int E  = in_sizes[2] / 2;
    int nb = (NN + 7) / 8;                 // warp-per-node blocks (256 thr)
    int ebt = (E + 255) / 256;

    k_combine<<<1, 1024>>>(Wd, Ws, Wc, Wms, Wmv);
    k_zero<<<(NN + 255) / 256, 256>>>();
    k_node<<<nb, 256>>>(x, Wns, Wnv);
    k_hist<<<ebt, 256>>>(ei, E);
    k_scan1<<<NB_SCAN, SCAN_B>>>();
    k_scan2<<<1, 128>>>();
    k_scan3<<<NB_SCAN, SCAN_B>>>();
    k_scatter<<<ebt, 256>>>(ei, pos, E);
    k_aggregate<<<nb, 256>>>(x, gam, bet, out);
}